// round 4
// baseline (speedup 1.0000x reference)
#include <cuda_runtime.h>
#include <cuda_fp16.h>

#define C_CH   256
#define NBINS  49
#define SPOS   14
#define PADH   129   // staging row: 128 floats + 1 pad

// NHWC fp16 scratch for all 4 pyramid levels: 256 ch * 87040 pixels = 44.5 MB
__device__ __half g_h[22282240];

__constant__ int   c_W[4]     = {256, 128, 64, 32};
__constant__ float c_scale[4] = {0.25f, 0.125f, 0.0625f, 0.03125f};
__constant__ int   c_base[4]  = {0, 65536, 81920, 86016};  // pixel offsets

// ---------------------------------------------------------------------------
// Fused NCHW fp32 -> NHWC fp16 transpose for all 4 levels in one launch.
// blockIdx.x = flat 32-pixel tile column across levels; blockIdx.y = ch tile.
// ---------------------------------------------------------------------------
__global__ void transpose_all(const float* __restrict__ f0,
                              const float* __restrict__ f1,
                              const float* __restrict__ f2,
                              const float* __restrict__ f3) {
    __shared__ float tile[32][33];
    int bx = blockIdx.x;
    const float* in; int HW, pix_base, hw0;
    if (bx < 2048)      { in = f0; HW = 65536; pix_base = 0;     hw0 = bx * 32; }
    else if (bx < 2560) { in = f1; HW = 16384; pix_base = 65536; hw0 = (bx - 2048) * 32; }
    else if (bx < 2688) { in = f2; HW = 4096;  pix_base = 81920; hw0 = (bx - 2560) * 32; }
    else                { in = f3; HW = 1024;  pix_base = 86016; hw0 = (bx - 2688) * 32; }
    int c0 = blockIdx.y * 32;
    int tx = threadIdx.x, ty = threadIdx.y;
#pragma unroll
    for (int k = 0; k < 4; ++k) {
        tile[ty + k * 8][tx] = in[(size_t)(c0 + ty + k * 8) * HW + hw0 + tx];
    }
    __syncthreads();
#pragma unroll
    for (int k = 0; k < 4; ++k) {
        g_h[(size_t)(pix_base + hw0 + ty + k * 8) * C_CH + c0 + tx] =
            __float2half_rn(tile[tx][ty + k * 8]);
    }
}

// ---------------------------------------------------------------------------
// Main kernel: block = (roi, channel-half). 8 warps; warp = contiguous bin
// chunk, lane o = channel quad (4 ch, uint2 load). Level-outer loop; cross-
// level max in swizzled smem staging.
// ---------------------------------------------------------------------------
__global__ __launch_bounds__(256, 5)
void roi_max_kernel(const float* __restrict__ rois, float* __restrict__ out) {
    extern __shared__ float sh[];                 // [49][129] staging, swizzled
    __shared__ int   s_lo[2][4][SPOS];            // [dim(x=0,y=1)][lvl][pos]
    __shared__ int   s_hi[2][4][SPOS];
    __shared__ float s_wl[2][4][SPOS];
    __shared__ float s_wh[2][4][SPOS];

    const int n = blockIdx.x;
    const int h = blockIdx.y;                     // channel half 0/1
    const int t = threadIdx.x;

    // --- precompute bilinear taps: 4 lvl x 2 dims x 14 positions = 112 tasks
    if (t < 112) {
        int lvl = t / 28;
        int rem = t % 28;
        int dim = rem / 14;            // 0 = x, 1 = y
        int s   = rem % 14;
        float scale = c_scale[lvl];
        float size  = (float)c_W[lvl];
        float start = rois[n * 5 + 1 + dim] * scale;
        float end   = rois[n * 5 + 3 + dim] * scale;
        float len   = fmaxf(end - start, 1.0f);
        float gpos  = (float)(s >> 1) + ((s & 1) ? 0.75f : 0.25f);
        float coord = start + gpos * (len * (1.0f / 7.0f));
        bool valid  = (coord > -1.0f) && (coord < size);
        float cc = fminf(fmaxf(coord, 0.0f), size - 1.0f);
        int lo = (int)cc;
        int hi = min(lo + 1, c_W[lvl] - 1);
        float wh = cc - (float)lo;
        float wl = 1.0f - wh;
        if (!valid) { wl = 0.0f; wh = 0.0f; }
        s_lo[dim][lvl][s] = lo;
        s_hi[dim][lvl][s] = hi;
        s_wl[dim][lvl][s] = wl;
        s_wh[dim][lvl][s] = wh;
    }
    __syncthreads();

    const int g  = t >> 5;                 // warp id 0..7
    const int o  = t & 31;                 // channel quad within half
    const int p0 = (NBINS * g) >> 3;       // contiguous bin range per warp
    const int p1 = (NBINS * (g + 1)) >> 3;
    const int r  = o >> 3;                 // swizzle rotation (0..3)

    const uint2* __restrict__ F = (const uint2*)g_h;   // 4 ch per uint2; 64/pixel

#pragma unroll
    for (int l = 0; l < 4; ++l) {
        const int W = c_W[l];
        const uint2* __restrict__ FL = F + (size_t)c_base[l] * 64 + h * 32 + o;
        for (int p = p0; p < p1; ++p) {
            int by = p / 7, bx = p - by * 7;
            float a0 = 0.f, a1 = 0.f, a2 = 0.f, a3 = 0.f;
#pragma unroll
            for (int sy = 0; sy < 2; ++sy) {
                int iy  = 2 * by + sy;
                int ylo = s_lo[1][l][iy], yhi = s_hi[1][l][iy];
                float wyl = s_wl[1][l][iy], wyh = s_wh[1][l][iy];
#pragma unroll
                for (int sx = 0; sx < 2; ++sx) {
                    int ix  = 2 * bx + sx;
                    int xlo = s_lo[0][l][ix], xhi = s_hi[0][l][ix];
                    float wxl = s_wl[0][l][ix], wxh = s_wh[0][l][ix];
                    float w00 = wyl * wxl, w01 = wyl * wxh;
                    float w10 = wyh * wxl, w11 = wyh * wxh;
                    uint2 v00 = FL[(ylo * W + xlo) * 64];
                    uint2 v01 = FL[(ylo * W + xhi) * 64];
                    uint2 v10 = FL[(yhi * W + xlo) * 64];
                    uint2 v11 = FL[(yhi * W + xhi) * 64];
                    float2 p00a = __half22float2(*(const __half2*)&v00.x);
                    float2 p00b = __half22float2(*(const __half2*)&v00.y);
                    float2 p01a = __half22float2(*(const __half2*)&v01.x);
                    float2 p01b = __half22float2(*(const __half2*)&v01.y);
                    float2 p10a = __half22float2(*(const __half2*)&v10.x);
                    float2 p10b = __half22float2(*(const __half2*)&v10.y);
                    float2 p11a = __half22float2(*(const __half2*)&v11.x);
                    float2 p11b = __half22float2(*(const __half2*)&v11.y);
                    a0 += w00*p00a.x + w01*p01a.x + w10*p10a.x + w11*p11a.x;
                    a1 += w00*p00a.y + w01*p01a.y + w10*p10a.y + w11*p11a.y;
                    a2 += w00*p00b.x + w01*p01b.x + w10*p10b.x + w11*p11b.x;
                    a3 += w00*p00b.y + w01*p01b.y + w10*p10b.y + w11*p11b.y;
                }
            }
            a0 *= 0.25f; a1 *= 0.25f; a2 *= 0.25f; a3 *= 0.25f;
            // swizzled staging: slot 4o + ((j + r)&3), conflict-free per store
            float* base = &sh[p * PADH + 4 * o];
            float v[4] = {a0, a1, a2, a3};
            if (l == 0) {
#pragma unroll
                for (int j = 0; j < 4; ++j) base[(j + r) & 3] = v[j];
            } else {
#pragma unroll
                for (int j = 0; j < 4; ++j) {
                    int s = (j + r) & 3;
                    base[s] = fmaxf(base[s], v[j]);
                }
            }
        }
    }
    __syncthreads();

    // coalesced drain: out[n][h*128 + c][p] (un-swizzle channel quad)
    float* __restrict__ O = out + (size_t)n * (C_CH * NBINS) + (size_t)h * 128 * NBINS;
#pragma unroll 7
    for (int idx = t; idx < 128 * NBINS; idx += 256) {
        int c = idx / 49;             // local channel 0..127
        int p = idx - c * 49;
        int qd = c >> 2;
        O[idx] = sh[p * PADH + 4 * qd + (((c & 3) + (qd >> 3)) & 3)];
    }
}

// ---------------------------------------------------------------------------
extern "C" void kernel_launch(void* const* d_in, const int* in_sizes, int n_in,
                              void* d_out, int out_size) {
    const float* f0   = (const float*)d_in[0];
    const float* f1   = (const float*)d_in[1];
    const float* f2   = (const float*)d_in[2];
    const float* f3   = (const float*)d_in[3];
    const float* rois = (const float*)d_in[4];
    int nrois = in_sizes[4] / 5;

    transpose_all<<<dim3(2720, 8), dim3(32, 8)>>>(f0, f1, f2, f3);

    size_t smem = (size_t)NBINS * PADH * sizeof(float);  // 25284 B
    cudaFuncSetAttribute(roi_max_kernel,
                         cudaFuncAttributeMaxDynamicSharedMemorySize, (int)smem);
    roi_max_kernel<<<dim3(nrois, 2), 256, smem>>>(rois, (float*)d_out);
}

// round 5
// speedup vs baseline: 1.2979x; 1.2979x over previous
#include <cuda_runtime.h>
#include <cuda_fp16.h>

#define C_CH   256
#define NBINS  49
#define SPOS   14
#define PAD    257

// NHWC fp16 scratch for all 4 pyramid levels: 256 ch * 87040 pixels = 44.5 MB
__device__ __half g_h[22282240];

__constant__ int   c_W[4]     = {256, 128, 64, 32};
__constant__ float c_scale[4] = {0.25f, 0.125f, 0.0625f, 0.03125f};
__constant__ int   c_base[4]  = {0, 65536, 81920, 86016};  // pixel offsets

// ---------------------------------------------------------------------------
// Fused NCHW fp32 -> NHWC fp16 transpose for all 4 levels in one launch.
// ---------------------------------------------------------------------------
__global__ void transpose_all(const float* __restrict__ f0,
                              const float* __restrict__ f1,
                              const float* __restrict__ f2,
                              const float* __restrict__ f3) {
    __shared__ float tile[32][33];
    int bx = blockIdx.x;
    const float* in; int HW, pix_base, hw0;
    if (bx < 2048)      { in = f0; HW = 65536; pix_base = 0;     hw0 = bx * 32; }
    else if (bx < 2560) { in = f1; HW = 16384; pix_base = 65536; hw0 = (bx - 2048) * 32; }
    else if (bx < 2688) { in = f2; HW = 4096;  pix_base = 81920; hw0 = (bx - 2560) * 32; }
    else                { in = f3; HW = 1024;  pix_base = 86016; hw0 = (bx - 2688) * 32; }
    int c0 = blockIdx.y * 32;
    int tx = threadIdx.x, ty = threadIdx.y;
#pragma unroll
    for (int k = 0; k < 4; ++k) {
        tile[ty + k * 8][tx] = in[(size_t)(c0 + ty + k * 8) * HW + hw0 + tx];
    }
    __syncthreads();
#pragma unroll
    for (int k = 0; k < 4; ++k) {
        g_h[(size_t)(pix_base + hw0 + ty + k * 8) * C_CH + c0 + tx] =
            __float2half_rn(tile[tx][ty + k * 8]);
    }
}

// ---------------------------------------------------------------------------
// Main kernel: one block per roi. 8 warps; warp = contiguous bin chunk,
// lane o = channel octet (uint4 = 8 fp16 ch). Level-outer for L1 reuse;
// cross-level max in swizzled smem staging. Tap weighting in HFMA2.
// ---------------------------------------------------------------------------
__global__ __launch_bounds__(256)
void roi_max_kernel(const float* __restrict__ rois, float* __restrict__ out) {
    extern __shared__ float sh[];                 // [49][257] staging, swizzled
    __shared__ int   s_lo[2][4][SPOS];            // [dim(x=0,y=1)][lvl][pos]
    __shared__ int   s_hi[2][4][SPOS];
    __shared__ float s_wl[2][4][SPOS];            // pre-scaled by 0.5 per axis
    __shared__ float s_wh[2][4][SPOS];

    const int n = blockIdx.x;
    const int t = threadIdx.x;

    // --- precompute bilinear taps: 4 lvl x 2 dims x 14 positions = 112 tasks
    if (t < 112) {
        int lvl = t / 28;
        int rem = t % 28;
        int dim = rem / 14;            // 0 = x, 1 = y
        int s   = rem % 14;
        float scale = c_scale[lvl];
        float size  = (float)c_W[lvl];
        float start = rois[n * 5 + 1 + dim] * scale;
        float end   = rois[n * 5 + 3 + dim] * scale;
        float len   = fmaxf(end - start, 1.0f);
        float gpos  = (float)(s >> 1) + ((s & 1) ? 0.75f : 0.25f);
        float coord = start + gpos * (len * (1.0f / 7.0f));
        bool valid  = (coord > -1.0f) && (coord < size);
        float cc = fminf(fmaxf(coord, 0.0f), size - 1.0f);
        int lo = (int)cc;
        int hi = min(lo + 1, c_W[lvl] - 1);
        float wh = cc - (float)lo;
        float wl = 1.0f - wh;
        if (!valid) { wl = 0.0f; wh = 0.0f; }
        s_lo[dim][lvl][s] = lo;
        s_hi[dim][lvl][s] = hi;
        s_wl[dim][lvl][s] = wl * 0.5f;   // fold 2x2-sample average into weights
        s_wh[dim][lvl][s] = wh * 0.5f;
    }
    __syncthreads();

    const int g  = t >> 5;                 // warp id 0..7
    const int o  = t & 31;                 // channel octet
    const int p0 = (NBINS * g) >> 3;       // contiguous bin range per warp
    const int p1 = (NBINS * (g + 1)) >> 3;
    const int r  = o >> 2;                 // swizzle rotation (0..7)

    const uint4* __restrict__ F = (const uint4*)g_h;   // 8 ch per uint4

#pragma unroll
    for (int l = 0; l < 4; ++l) {
        const int W = c_W[l];
        const uint4* __restrict__ FL = F + (size_t)c_base[l] * 32 + o;
        for (int p = p0; p < p1; ++p) {
            int by = p / 7, bx = p - by * 7;
            float a[8];
#pragma unroll
            for (int j = 0; j < 8; ++j) a[j] = 0.0f;
#pragma unroll
            for (int sy = 0; sy < 2; ++sy) {
                int iy  = 2 * by + sy;
                int ylo = s_lo[1][l][iy], yhi = s_hi[1][l][iy];
                float wyl = s_wl[1][l][iy], wyh = s_wh[1][l][iy];
                int yblo = ylo * W, ybhi = yhi * W;
#pragma unroll
                for (int sx = 0; sx < 2; ++sx) {
                    int ix  = 2 * bx + sx;
                    int xlo = s_lo[0][l][ix], xhi = s_hi[0][l][ix];
                    float wxl = s_wl[0][l][ix], wxh = s_wh[0][l][ix];
                    __half2 h00 = __float2half2_rn(wyl * wxl);
                    __half2 h01 = __float2half2_rn(wyl * wxh);
                    __half2 h10 = __float2half2_rn(wyh * wxl);
                    __half2 h11 = __float2half2_rn(wyh * wxh);
                    uint4 v00 = FL[(yblo + xlo) * 32];
                    uint4 v01 = FL[(yblo + xhi) * 32];
                    uint4 v10 = FL[(ybhi + xlo) * 32];
                    uint4 v11 = FL[(ybhi + xhi) * 32];
                    const __half2* q00 = (const __half2*)&v00;
                    const __half2* q01 = (const __half2*)&v01;
                    const __half2* q10 = (const __half2*)&v10;
                    const __half2* q11 = (const __half2*)&v11;
#pragma unroll
                    for (int i = 0; i < 4; ++i) {
                        __half2 s2 = __hmul2(h00, q00[i]);
                        s2 = __hfma2(h01, q01[i], s2);
                        s2 = __hfma2(h10, q10[i], s2);
                        s2 = __hfma2(h11, q11[i], s2);
                        float2 f = __half22float2(s2);   // fp32 sample accumulate
                        a[2*i]   += f.x;
                        a[2*i+1] += f.y;
                    }
                }
            }
            // swizzled staging update: slot 8o + ((j+r)&7) is bank-conflict-free
            float* base = &sh[p * PAD + 8 * o];
            if (l == 0) {
#pragma unroll
                for (int j = 0; j < 8; ++j) base[(j + r) & 7] = a[j];
            } else {
#pragma unroll
                for (int j = 0; j < 8; ++j) {
                    int s = (j + r) & 7;
                    base[s] = fmaxf(base[s], a[j]);
                }
            }
        }
    }
    __syncthreads();

    // coalesced drain: out[n][c][p] flat = c*49 + p (un-swizzle channel)
    float* __restrict__ O = out + (size_t)n * (C_CH * NBINS);
#pragma unroll 7
    for (int idx = t; idx < C_CH * NBINS; idx += 256) {
        int c = idx / 49;
        int p = idx - c * 49;
        int oo = c >> 3;
        O[idx] = sh[p * PAD + 8 * oo + (((c & 7) + (oo >> 2)) & 7)];
    }
}

// ---------------------------------------------------------------------------
extern "C" void kernel_launch(void* const* d_in, const int* in_sizes, int n_in,
                              void* d_out, int out_size) {
    const float* f0   = (const float*)d_in[0];
    const float* f1   = (const float*)d_in[1];
    const float* f2   = (const float*)d_in[2];
    const float* f3   = (const float*)d_in[3];
    const float* rois = (const float*)d_in[4];
    int nrois = in_sizes[4] / 5;

    transpose_all<<<dim3(2720, 8), dim3(32, 8)>>>(f0, f1, f2, f3);

    size_t smem = (size_t)NBINS * PAD * sizeof(float);  // 50372 B
    cudaFuncSetAttribute(roi_max_kernel,
                         cudaFuncAttributeMaxDynamicSharedMemorySize, (int)smem);
    roi_max_kernel<<<nrois, 256, smem>>>(rois, (float*)d_out);
}

// round 6
// speedup vs baseline: 1.4819x; 1.1417x over previous
#include <cuda_runtime.h>
#include <cuda_fp16.h>

#define C_CH    256
#define NBINS   49
#define SPOS    14
#define ROW_H2  132                      // half2 per staging row (128 + pad, 16B-aligned rows)
#define STAGE_H2 (NBINS * ROW_H2)        // 6468 half2 = 25872 B
#define NTAB    (4 * NBINS * 16)         // 3136 entries
#define SMEM_DYN (STAGE_H2 * 4 + NTAB * 8)   // 25872 + 25088 = 50960 B

// NHWC fp16 scratch for all 4 pyramid levels: 256 ch * 87040 pixels = 44.5 MB
__device__ __half g_h[22282240];

__constant__ int   c_W[4]     = {256, 128, 64, 32};
__constant__ float c_scale[4] = {0.25f, 0.125f, 0.0625f, 0.03125f};
__constant__ int   c_base[4]  = {0, 65536, 81920, 86016};  // pixel offsets

// ---------------------------------------------------------------------------
// Fused NCHW fp32 -> NHWC fp16 transpose for all 4 levels in one launch.
// ---------------------------------------------------------------------------
__global__ void transpose_all(const float* __restrict__ f0,
                              const float* __restrict__ f1,
                              const float* __restrict__ f2,
                              const float* __restrict__ f3) {
    __shared__ float tile[32][33];
    int bx = blockIdx.x;
    const float* in; int HW, pix_base, hw0;
    if (bx < 2048)      { in = f0; HW = 65536; pix_base = 0;     hw0 = bx * 32; }
    else if (bx < 2560) { in = f1; HW = 16384; pix_base = 65536; hw0 = (bx - 2048) * 32; }
    else if (bx < 2688) { in = f2; HW = 4096;  pix_base = 81920; hw0 = (bx - 2560) * 32; }
    else                { in = f3; HW = 1024;  pix_base = 86016; hw0 = (bx - 2688) * 32; }
    int c0 = blockIdx.y * 32;
    int tx = threadIdx.x, ty = threadIdx.y;
#pragma unroll
    for (int k = 0; k < 4; ++k) {
        tile[ty + k * 8][tx] = in[(size_t)(c0 + ty + k * 8) * HW + hw0 + tx];
    }
    __syncthreads();
#pragma unroll
    for (int k = 0; k < 4; ++k) {
        g_h[(size_t)(pix_base + hw0 + ty + k * 8) * C_CH + c0 + tx] =
            __float2half_rn(tile[tx][ty + k * 8]);
    }
}

// ---------------------------------------------------------------------------
// Main kernel: one block per roi. Table-driven taps; lane o = channel octet
// (uint4 = 8 fp16 ch); warp = contiguous bin chunk; level-outer; cross-level
// max in fp16 smem staging.
// ---------------------------------------------------------------------------
__global__ __launch_bounds__(256, 4)
void roi_max_kernel(const float* __restrict__ rois, float* __restrict__ out) {
    extern __shared__ __align__(16) char dyn[];
    __half2* sh2 = (__half2*)dyn;                       // staging [49][132]
    int2*    tab = (int2*)(dyn + STAGE_H2 * 4);         // [4][49][16] tap table

    __shared__ int   s_lo[2][4][SPOS];
    __shared__ int   s_hi[2][4][SPOS];
    __shared__ float s_wl[2][4][SPOS];   // pre-scaled by 0.5 (bin average fold)
    __shared__ float s_wh[2][4][SPOS];

    const int n = blockIdx.x;
    const int t = threadIdx.x;

    // --- phase 1: 1D bilinear taps, 4 lvl x 2 dims x 14 positions
    if (t < 112) {
        int lvl = t / 28;
        int rem = t % 28;
        int dim = rem / 14;
        int s   = rem % 14;
        float scale = c_scale[lvl];
        float size  = (float)c_W[lvl];
        float start = rois[n * 5 + 1 + dim] * scale;
        float end   = rois[n * 5 + 3 + dim] * scale;
        float len   = fmaxf(end - start, 1.0f);
        float gpos  = (float)(s >> 1) + ((s & 1) ? 0.75f : 0.25f);
        float coord = start + gpos * (len * (1.0f / 7.0f));
        bool valid  = (coord > -1.0f) && (coord < size);
        float cc = fminf(fmaxf(coord, 0.0f), size - 1.0f);
        int lo = (int)cc;
        int hi = min(lo + 1, c_W[lvl] - 1);
        float wh = cc - (float)lo;
        float wl = 1.0f - wh;
        if (!valid) { wl = 0.0f; wh = 0.0f; }
        s_lo[dim][lvl][s] = lo;
        s_hi[dim][lvl][s] = hi;
        s_wl[dim][lvl][s] = wl * 0.5f;
        s_wh[dim][lvl][s] = wh * 0.5f;
    }
    __syncthreads();

    // --- phase 2: 2D tap table {pixoff*32, half2 weight}
    for (int i = t; i < NTAB; i += 256) {
        int e  = i & 15;
        int pb = i >> 4;                 // 0..195
        int l  = pb / NBINS;
        int p  = pb - l * NBINS;
        int by = p / 7, bx = p - by * 7;
        int sy = e >> 3, sx = (e >> 2) & 1, ty = (e >> 1) & 1, tx = e & 1;
        int iy = 2 * by + sy, ix = 2 * bx + sx;
        int   yi = ty ? s_hi[1][l][iy] : s_lo[1][l][iy];
        float wy = ty ? s_wh[1][l][iy] : s_wl[1][l][iy];
        int   xi = tx ? s_hi[0][l][ix] : s_lo[0][l][ix];
        float wx = tx ? s_wh[0][l][ix] : s_wl[0][l][ix];
        __half2 w2 = __float2half2_rn(wy * wx);
        int2 ent;
        ent.x = (yi * c_W[l] + xi) * 32;         // uint4 index, lane added later
        ent.y = *(int*)&w2;
        tab[i] = ent;
    }
    __syncthreads();

    const int g  = t >> 5;                 // warp id 0..7
    const int o  = t & 31;                 // channel octet
    const int p0 = (NBINS * g) >> 3;
    const int p1 = (NBINS * (g + 1)) >> 3;

    const uint4* __restrict__ F = (const uint4*)g_h;

#pragma unroll
    for (int l = 0; l < 4; ++l) {
        const uint4* __restrict__ FL = F + (size_t)c_base[l] * 32 + o;
        const int2*  __restrict__ TB = tab + l * (NBINS * 16);
        for (int p = p0; p < p1; ++p) {
            const int2* tp = TB + p * 16;
            float a0 = 0.f, a1 = 0.f, a2 = 0.f, a3 = 0.f;
            float a4 = 0.f, a5 = 0.f, a6 = 0.f, a7 = 0.f;
#pragma unroll
            for (int s = 0; s < 4; ++s) {
                __half2 c0h, c1h, c2h, c3h;
#pragma unroll
                for (int k = 0; k < 4; ++k) {
                    int2 ent = tp[s * 4 + k];
                    __half2 w2 = *(__half2*)&ent.y;
                    uint4 v = FL[ent.x];
                    const __half2* q = (const __half2*)&v;
                    if (k == 0) {
                        c0h = __hmul2(w2, q[0]); c1h = __hmul2(w2, q[1]);
                        c2h = __hmul2(w2, q[2]); c3h = __hmul2(w2, q[3]);
                    } else {
                        c0h = __hfma2(w2, q[0], c0h); c1h = __hfma2(w2, q[1], c1h);
                        c2h = __hfma2(w2, q[2], c2h); c3h = __hfma2(w2, q[3], c3h);
                    }
                }
                float2 f0 = __half22float2(c0h), f1 = __half22float2(c1h);
                float2 f2 = __half22float2(c2h), f3 = __half22float2(c3h);
                a0 += f0.x; a1 += f0.y; a2 += f1.x; a3 += f1.y;
                a4 += f2.x; a5 += f2.y; a6 += f3.x; a7 += f3.y;
            }
            // fp16 staging: one uint4 per lane, conflict-free
            __half2 r0 = __floats2half2_rn(a0, a1);
            __half2 r1 = __floats2half2_rn(a2, a3);
            __half2 r2 = __floats2half2_rn(a4, a5);
            __half2 r3 = __floats2half2_rn(a6, a7);
            uint4* dst = (uint4*)(sh2 + p * ROW_H2 + o * 4);
            if (l == 0) {
                uint4 nw;
                ((__half2*)&nw)[0] = r0; ((__half2*)&nw)[1] = r1;
                ((__half2*)&nw)[2] = r2; ((__half2*)&nw)[3] = r3;
                *dst = nw;
            } else {
                uint4 old = *dst;
                __half2* oh = (__half2*)&old;
                oh[0] = __hmax2(oh[0], r0); oh[1] = __hmax2(oh[1], r1);
                oh[2] = __hmax2(oh[2], r2); oh[3] = __hmax2(oh[3], r3);
                *dst = old;
            }
        }
    }
    __syncthreads();

    // coalesced drain: out[n][c][p], channel c == half index c within row
    const __half* shh = (const __half*)sh2;
    float* __restrict__ O = out + (size_t)n * (C_CH * NBINS);
#pragma unroll 7
    for (int idx = t; idx < C_CH * NBINS; idx += 256) {
        int c = idx / 49;
        int p = idx - c * 49;
        O[idx] = __half2float(shh[p * (ROW_H2 * 2) + c]);
    }
}

// ---------------------------------------------------------------------------
extern "C" void kernel_launch(void* const* d_in, const int* in_sizes, int n_in,
                              void* d_out, int out_size) {
    const float* f0   = (const float*)d_in[0];
    const float* f1   = (const float*)d_in[1];
    const float* f2   = (const float*)d_in[2];
    const float* f3   = (const float*)d_in[3];
    const float* rois = (const float*)d_in[4];
    int nrois = in_sizes[4] / 5;

    transpose_all<<<dim3(2720, 8), dim3(32, 8)>>>(f0, f1, f2, f3);

    cudaFuncSetAttribute(roi_max_kernel,
                         cudaFuncAttributeMaxDynamicSharedMemorySize, SMEM_DYN);
    roi_max_kernel<<<nrois, 256, SMEM_DYN>>>(rois, (float*)d_out);
}